// round 8
// baseline (speedup 1.0000x reference)
#include <cuda_runtime.h>
#include <cuda_fp16.h>
#include <cstdint>

#define NTILES 8192            // 524288 pixels / 64 per tile
#define EPSV   1e-6f

// smem byte layout
#define WPITCH   1056
#define S_W      0              // weights: 64 cpair-rows x 1056 B = 67584
#define S_HALF   67584          // 4 stages x 16384 B (64 px x 256 B)
#define S_MB     133120         // full[4] @ +0, empty[4] @ +32
#define SMEM_TOTAL 133184

__device__ __forceinline__ void mma_f16(float* c, uint32_t a0, uint32_t a1,
                                        uint32_t a2, uint32_t a3,
                                        uint32_t b0, uint32_t b1) {
    asm volatile(
        "mma.sync.aligned.m16n8k16.row.col.f32.f16.f16.f32 "
        "{%0,%1,%2,%3},{%4,%5,%6,%7},{%8,%9},{%0,%1,%2,%3};\n"
        : "+f"(c[0]), "+f"(c[1]), "+f"(c[2]), "+f"(c[3])
        : "r"(a0), "r"(a1), "r"(a2), "r"(a3), "r"(b0), "r"(b1));
}

__device__ __forceinline__ float2 ldcg2(const float2* p) {
    float2 v;
    asm("ld.global.cg.v2.f32 {%0,%1}, [%2];" : "=f"(v.x), "=f"(v.y) : "l"(p));
    return v;
}

__device__ __forceinline__ uint32_t h2u(__half2 h) {
    return *reinterpret_cast<uint32_t*>(&h);
}

#define MB_INIT(addr, cnt) \
    asm volatile("mbarrier.init.shared.b64 [%0], %1;" :: "r"(addr), "r"(cnt) : "memory")
#define MB_ARRIVE(addr) \
    asm volatile("mbarrier.arrive.shared.b64 _, [%0];" :: "r"(addr) : "memory")

#define WAIT_PARITY(addr, ph) do { \
    uint32_t _m = (addr), _p = (ph), _done; \
    asm volatile("{\n\t.reg .pred p;\n\t" \
        "mbarrier.try_wait.parity.acquire.cta.shared::cta.b64 p, [%1], %2;\n\t" \
        "selp.b32 %0, 1, 0, p;\n\t}" : "=r"(_done) : "r"(_m), "r"(_p) : "memory"); \
    if (!_done) { \
        asm volatile("{\n\t.reg .pred P1;\n\t" \
            "WL_%=:\n\t" \
            "mbarrier.try_wait.parity.acquire.cta.shared::cta.b64 P1, [%0], %1, 0x989680;\n\t" \
            "@P1 bra.uni WD_%=;\n\tbra.uni WL_%=;\n\tWD_%=:\n\t}" \
            :: "r"(_m), "r"(_p) : "memory"); \
    } \
} while (0)

__global__ __launch_bounds__(384, 1)
void avnn_w8(const float* __restrict__ x,
             const float* __restrict__ wx,
             const float* __restrict__ bx,
             const float* __restrict__ wy,
             const float* __restrict__ by,
             float2* __restrict__ out) {
    extern __shared__ char smem[];
    uint32_t sbase;
    asm("{ .reg .u64 t; cvta.to.shared.u64 t, %1; cvt.u32.u64 %0, t; }"
        : "=r"(sbase) : "l"((const void*)smem));

    const int tid = threadIdx.x, wid = tid >> 5, lane = tid & 31;
    const int grid = gridDim.x;
    char* smW = smem + S_W;

    // ---- stage weights once: sW[cpair][o] = (wx_lo, wx_hi, wy_lo, wy_hi) ----
    for (int idx = tid; idx < 128 * 128; idx += 384) {
        int o = idx >> 7, c = idx & 127;
        int cp = c >> 1, hi = c & 1;
        __half* w = (__half*)(smW + cp * WPITCH + o * 8);
        w[hi]     = __float2half_rn(wx[idx]);
        w[2 + hi] = __float2half_rn(wy[idx]);
    }
    if (tid == 0) {
        #pragma unroll
        for (int i = 0; i < 4; i++) {
            MB_INIT(sbase + S_MB + i * 8, 128);        // full
            MB_INIT(sbase + S_MB + 32 + i * 8, 256);   // empty
        }
    }
    __syncthreads();

    if (wid >= 8) {
        // ======================= producers (4 warps) =======================
        const int ptid = tid - 256, pwid = ptid >> 5, plane = ptid & 31;
        const float2* xf2 = (const float2*)x;
        float2 rb[32];

        // load chunk (tt, ch): this warp's 16 c-rows x 64 px, into registers
        #define LOADCH(tt, ch) do { \
            int _b = (tt) >> 10, _pp = ((tt) & 1023) << 6; \
            const float2* _gp = xf2 \
                + (((size_t)(_b * 128 + (ch) * 64 + pwid * 16)) << 16) \
                + _pp + plane; \
            _Pragma("unroll") \
            for (int _t = 0; _t < 4; _t++) { \
                _Pragma("unroll") \
                for (int _ph = 0; _ph < 2; _ph++) { \
                    const float2* _p = _gp + (((size_t)(2 * _t)) << 16) + 32 * _ph; \
                    rb[(_t * 2 + _ph) * 4 + 0] = ldcg2(_p); \
                    rb[(_t * 2 + _ph) * 4 + 1] = ldcg2(_p + (1 << 16)); \
                    rb[(_t * 2 + _ph) * 4 + 2] = ldcg2(_p + (8 << 16)); \
                    rb[(_t * 2 + _ph) * 4 + 3] = ldcg2(_p + (9 << 16)); \
                } \
            } \
        } while (0)

        // transform register chunk -> half buffer stage (s&3)
        #define TRANSFORM_R(stg) do { \
            char* _hb = smem + S_HALF + (stg) * 16384; \
            _Pragma("unroll") \
            for (int _t = 0; _t < 4; _t++) { \
                _Pragma("unroll") \
                for (int _ph = 0; _ph < 2; _ph++) { \
                    const int _px = plane + 32 * _ph; \
                    float2 v0 = rb[(_t * 2 + _ph) * 4 + 0]; \
                    float2 v1 = rb[(_t * 2 + _ph) * 4 + 1]; \
                    float2 v2 = rb[(_t * 2 + _ph) * 4 + 2]; \
                    float2 v3 = rb[(_t * 2 + _ph) * 4 + 3]; \
                    float g0 = __fdividef(v0.x * v0.y, fabsf(v0.x) + EPSV); \
                    float g1 = __fdividef(v1.x * v1.y, fabsf(v1.x) + EPSV); \
                    float g2 = __fdividef(v2.x * v2.y, fabsf(v2.x) + EPSV); \
                    float g3 = __fdividef(v3.x * v3.y, fabsf(v3.x) + EPSV); \
                    uint4 st; \
                    st.x = h2u(__floats2half2_rn(v0.x, v1.x)); \
                    st.y = h2u(__floats2half2_rn(v2.x, v3.x)); \
                    st.z = h2u(__floats2half2_rn(g0, g1)); \
                    st.w = h2u(__floats2half2_rn(g2, g3)); \
                    uint32_t slot = (uint32_t)(((pwid ^ (_px & 3)) << 2) \
                                               | (_t ^ ((_px >> 1) & 3))); \
                    *(uint4*)(_hb + _px * 256 + slot * 16) = st; \
                } \
            } \
        } while (0)

        LOADCH(blockIdx.x, 0);

        int s = 0;
        for (int t = blockIdx.x; t < NTILES; t += grid) {
            // chunk 0 of tile t
            WAIT_PARITY(sbase + S_MB + 32 + (s & 3) * 8, ((s >> 2) + 1) & 1);
            TRANSFORM_R(s & 3);
            MB_ARRIVE(sbase + S_MB + (s & 3) * 8);
            LOADCH(t, 1);
            s++;
            // chunk 1 of tile t
            WAIT_PARITY(sbase + S_MB + 32 + (s & 3) * 8, ((s >> 2) + 1) & 1);
            TRANSFORM_R(s & 3);
            MB_ARRIVE(sbase + S_MB + (s & 3) * 8);
            int tn = t + grid;
            if (tn < NTILES) LOADCH(tn, 0);
            s++;
        }
    } else {
        // ======================= consumers (8 warps) =======================
        const int gid = lane >> 2, q = lane & 3;
        const int mbase = (wid & 1) * 32;      // pixel base (2 M-warps)
        const int nbase = (wid >> 1) * 32;     // o base     (4 N-warps)
        const int x3 = gid & 3;

        float bxv[4][2], byv[4][2];
        #pragma unroll
        for (int nt = 0; nt < 4; nt++) {
            int o0 = nbase + nt * 8 + 2 * q;
            bxv[nt][0] = __ldg(bx + o0); bxv[nt][1] = __ldg(bx + o0 + 1);
            byv[nt][0] = __ldg(by + o0); byv[nt][1] = __ldg(by + o0 + 1);
        }

        uint32_t abm[4];
        #pragma unroll
        for (int m = 0; m < 4; m++) {
            int px = mbase + gid + 8 * m;
            abm[m] = (uint32_t)px * 256u + (uint32_t)((q ^ (gid >> 1)) << 4);
        }
        const char* pB = smW + q * WPITCH + (nbase + gid) * 8;

        int s = 0;
        for (int t = blockIdx.x; t < NTILES; t += grid) {
            float acc[2][2][4][4];
            #pragma unroll
            for (int g = 0; g < 2; g++)
                #pragma unroll
                for (int mt = 0; mt < 2; mt++)
                    #pragma unroll
                    for (int nt = 0; nt < 4; nt++)
                        #pragma unroll
                        for (int i = 0; i < 4; i++) acc[g][mt][nt][i] = 0.f;

            #pragma unroll
            for (int ch = 0; ch < 2; ch++, s++) {
                WAIT_PARITY(sbase + S_MB + (s & 3) * 8, (s >> 2) & 1);
                const char* hb = smem + S_HALF + (s & 3) * 16384;

                #pragma unroll
                for (int k16l = 0; k16l < 4; k16l++) {
                    const uint32_t koff = (uint32_t)((k16l ^ x3) << 6);
                    uint4 A0 = *(const uint4*)(hb + abm[0] + koff);
                    uint4 A1 = *(const uint4*)(hb + abm[1] + koff);
                    uint4 A2 = *(const uint4*)(hb + abm[2] + koff);
                    uint4 A3 = *(const uint4*)(hb + abm[3] + koff);
                    const char* _pb = pB + (ch * 4 + k16l) * (8 * WPITCH);
                    #pragma unroll
                    for (int nt = 0; nt < 4; nt++) {
                        uint2 B0 = *(const uint2*)(_pb + nt * 64);
                        uint2 B1 = *(const uint2*)(_pb + 4 * WPITCH + nt * 64);
                        mma_f16(acc[0][0][nt], A0.x, A1.x, A0.y, A1.y, B0.x, B1.x);
                        mma_f16(acc[0][1][nt], A2.x, A3.x, A2.y, A3.y, B0.x, B1.x);
                        mma_f16(acc[1][0][nt], A0.z, A1.z, A0.w, A1.w, B0.y, B1.y);
                        mma_f16(acc[1][1][nt], A2.z, A3.z, A2.w, A3.w, B0.y, B1.y);
                    }
                }
                MB_ARRIVE(sbase + S_MB + 32 + (s & 3) * 8);
            }

            // ---- epilogue ----
            const int b = t >> 10, pp = (t & 1023) << 6;
            const size_t tb = ((size_t)b << 23) + (size_t)pp;
            #pragma unroll
            for (int nt = 0; nt < 4; nt++) {
                const int o0 = nbase + nt * 8 + 2 * q;
                #pragma unroll
                for (int io = 0; io < 2; io++) {
                    float2* rowp = out + tb + ((size_t)(o0 + io) << 16);
                    #pragma unroll
                    for (int mt = 0; mt < 2; mt++) {
                        #pragma unroll
                        for (int ih = 0; ih < 2; ih++) {
                            const int pix = mbase + mt * 16 + gid + ih * 8;
                            float a = acc[0][mt][nt][ih * 2 + io] + bxv[nt][io];
                            float g = acc[1][mt][nt][ih * 2 + io] + byv[nt][io];
                            rowp[pix] = make_float2(fmaxf(a, 0.f), g);
                        }
                    }
                }
            }
        }
    }
}

extern "C" void kernel_launch(void* const* d_in, const int* in_sizes, int n_in,
                              void* d_out, int out_size) {
    const float* x  = (const float*)d_in[0];
    const float* wx = (const float*)d_in[1];
    const float* bx = (const float*)d_in[2];
    const float* wy = (const float*)d_in[3];
    const float* by = (const float*)d_in[4];
    float2* out = (float2*)d_out;

    int nsm = 148;
    cudaDeviceGetAttribute(&nsm, cudaDevAttrMultiProcessorCount, 0);

    cudaFuncSetAttribute(avnn_w8, cudaFuncAttributeMaxDynamicSharedMemorySize,
                         SMEM_TOTAL);
    avnn_w8<<<nsm, 384, SMEM_TOTAL>>>(x, wx, bx, wy, by, out);
}

// round 9
// speedup vs baseline: 1.1228x; 1.1228x over previous
#include <cuda_runtime.h>
#include <cuda_fp16.h>
#include <cstdint>

#define NTILES 8192            // 524288 pixels / 64 per tile
#define EPSV   1e-6f

// smem byte layout
#define WPITCH   2080           // 128 o x 16B + 32B pad (520 words = 8 mod 32)
#define S_W      0              // weights: 32 rows x 2080 B = 66560
#define S_HALF   66560          // 4 stages x 16384 B (64 px x 256 B)
#define S_MB     132096         // full[4] @ +0, empty[4] @ +32
#define SMEM_TOTAL 132160

__device__ __forceinline__ void mma_f16(float* c, uint32_t a0, uint32_t a1,
                                        uint32_t a2, uint32_t a3,
                                        uint32_t b0, uint32_t b1) {
    asm volatile(
        "mma.sync.aligned.m16n8k16.row.col.f32.f16.f16.f32 "
        "{%0,%1,%2,%3},{%4,%5,%6,%7},{%8,%9},{%0,%1,%2,%3};\n"
        : "+f"(c[0]), "+f"(c[1]), "+f"(c[2]), "+f"(c[3])
        : "r"(a0), "r"(a1), "r"(a2), "r"(a3), "r"(b0), "r"(b1));
}

__device__ __forceinline__ float2 ldcg2(const float2* p) {
    float2 v;
    asm("ld.global.cg.v2.f32 {%0,%1}, [%2];" : "=f"(v.x), "=f"(v.y) : "l"(p));
    return v;
}

__device__ __forceinline__ uint32_t h2u(__half2 h) {
    return *reinterpret_cast<uint32_t*>(&h);
}

#define MB_INIT(addr, cnt) \
    asm volatile("mbarrier.init.shared.b64 [%0], %1;" :: "r"(addr), "r"(cnt) : "memory")
#define MB_ARRIVE(addr) \
    asm volatile("mbarrier.arrive.shared.b64 _, [%0];" :: "r"(addr) : "memory")

#define WAIT_PARITY(addr, ph) do { \
    uint32_t _m = (addr), _p = (ph), _done; \
    asm volatile("{\n\t.reg .pred p;\n\t" \
        "mbarrier.try_wait.parity.acquire.cta.shared::cta.b64 p, [%1], %2;\n\t" \
        "selp.b32 %0, 1, 0, p;\n\t}" : "=r"(_done) : "r"(_m), "r"(_p) : "memory"); \
    if (!_done) { \
        asm volatile("{\n\t.reg .pred P1;\n\t" \
            "WL_%=:\n\t" \
            "mbarrier.try_wait.parity.acquire.cta.shared::cta.b64 P1, [%0], %1, 0x989680;\n\t" \
            "@P1 bra.uni WD_%=;\n\tbra.uni WL_%=;\n\tWD_%=:\n\t}" \
            :: "r"(_m), "r"(_p) : "memory"); \
    } \
} while (0)

__global__ __launch_bounds__(384, 1)
void avnn_w9(const float* __restrict__ x,
             const float* __restrict__ wx,
             const float* __restrict__ bx,
             const float* __restrict__ wy,
             const float* __restrict__ by,
             float2* __restrict__ out) {
    extern __shared__ char smem[];
    uint32_t sbase;
    asm("{ .reg .u64 t; cvta.to.shared.u64 t, %1; cvt.u32.u64 %0, t; }"
        : "=r"(sbase) : "l"((const void*)smem));

    const int tid = threadIdx.x, wid = tid >> 5, lane = tid & 31;
    const int grid = gridDim.x;
    char* smW = smem + S_W;

    // ---- stage weights once ----
    // row = k16*4 + qd (qd = quad), cell[o] 16B = (wx_b0, wx_b1, wy_b0, wy_b1) half2s
    // b0 = k pairs (2qd, 2qd+1); b1 = (2qd+8, 2qd+9) within the k16 block
    for (int idx = tid; idx < 128 * 128; idx += 384) {
        int o = idx >> 7, c = idx & 127;
        int k16 = c >> 4, r = c & 15;
        int part = r >> 3, qd = (r & 7) >> 1, hf = r & 1;
        __half* w = (__half*)(smW + (k16 * 4 + qd) * WPITCH + o * 16);
        w[part * 2 + hf]     = __float2half_rn(wx[idx]);
        w[4 + part * 2 + hf] = __float2half_rn(wy[idx]);
    }
    if (tid == 0) {
        #pragma unroll
        for (int i = 0; i < 4; i++) {
            MB_INIT(sbase + S_MB + i * 8, 128);        // full
            MB_INIT(sbase + S_MB + 32 + i * 8, 256);   // empty
        }
    }
    __syncthreads();

    if (wid >= 8) {
        // ======================= producers (4 warps) =======================
        const int ptid = tid - 256, pwid = ptid >> 5, plane = ptid & 31;
        const float2* xf2 = (const float2*)x;
        float2 rb0[32], rb1[32];

        #define LOADCH(rbv, tt, ch) do { \
            int _b = (tt) >> 10, _pp = ((tt) & 1023) << 6; \
            const float2* _gp = xf2 \
                + (((size_t)(_b * 128 + (ch) * 64 + pwid * 16)) << 16) \
                + _pp + plane; \
            _Pragma("unroll") \
            for (int _t = 0; _t < 4; _t++) { \
                _Pragma("unroll") \
                for (int _ph = 0; _ph < 2; _ph++) { \
                    const float2* _p = _gp + (((size_t)(2 * _t)) << 16) + 32 * _ph; \
                    rbv[(_t * 2 + _ph) * 4 + 0] = ldcg2(_p); \
                    rbv[(_t * 2 + _ph) * 4 + 1] = ldcg2(_p + (1 << 16)); \
                    rbv[(_t * 2 + _ph) * 4 + 2] = ldcg2(_p + (8 << 16)); \
                    rbv[(_t * 2 + _ph) * 4 + 3] = ldcg2(_p + (9 << 16)); \
                } \
            } \
        } while (0)

        #define TRANSFORM_R(rbv, stg) do { \
            char* _hb = smem + S_HALF + (stg) * 16384; \
            _Pragma("unroll") \
            for (int _t = 0; _t < 4; _t++) { \
                _Pragma("unroll") \
                for (int _ph = 0; _ph < 2; _ph++) { \
                    const int _px = plane + 32 * _ph; \
                    float2 v0 = rbv[(_t * 2 + _ph) * 4 + 0]; \
                    float2 v1 = rbv[(_t * 2 + _ph) * 4 + 1]; \
                    float2 v2 = rbv[(_t * 2 + _ph) * 4 + 2]; \
                    float2 v3 = rbv[(_t * 2 + _ph) * 4 + 3]; \
                    float g0 = __fdividef(v0.x * v0.y, fabsf(v0.x) + EPSV); \
                    float g1 = __fdividef(v1.x * v1.y, fabsf(v1.x) + EPSV); \
                    float g2 = __fdividef(v2.x * v2.y, fabsf(v2.x) + EPSV); \
                    float g3 = __fdividef(v3.x * v3.y, fabsf(v3.x) + EPSV); \
                    uint4 st; \
                    st.x = h2u(__floats2half2_rn(v0.x, v1.x)); \
                    st.y = h2u(__floats2half2_rn(v2.x, v3.x)); \
                    st.z = h2u(__floats2half2_rn(g0, g1)); \
                    st.w = h2u(__floats2half2_rn(g2, g3)); \
                    uint32_t slot = (uint32_t)(((pwid ^ (_px & 3)) << 2) \
                                               | (_t ^ ((_px >> 1) & 3))); \
                    *(uint4*)(_hb + _px * 256 + slot * 16) = st; \
                } \
            } \
        } while (0)

        LOADCH(rb0, blockIdx.x, 0);

        int s = 0;
        for (int t = blockIdx.x; t < NTILES; t += grid) {
            // load ahead: chunk 1 of tile t; transform chunk 0 from rb0
            LOADCH(rb1, t, 1);
            WAIT_PARITY(sbase + S_MB + 32 + (s & 3) * 8, ((s >> 2) + 1) & 1);
            TRANSFORM_R(rb0, s & 3);
            MB_ARRIVE(sbase + S_MB + (s & 3) * 8);
            s++;
            // load ahead: chunk 0 of next tile; transform chunk 1 from rb1
            int tn = t + grid;
            if (tn < NTILES) LOADCH(rb0, tn, 0);
            WAIT_PARITY(sbase + S_MB + 32 + (s & 3) * 8, ((s >> 2) + 1) & 1);
            TRANSFORM_R(rb1, s & 3);
            MB_ARRIVE(sbase + S_MB + (s & 3) * 8);
            s++;
        }
    } else {
        // ======================= consumers (8 warps) =======================
        const int gid = lane >> 2, q = lane & 3;
        const int mbase = (wid & 1) * 32;      // pixel base (2 M-warps)
        const int nbase = (wid >> 1) * 32;     // o base     (4 N-warps)
        const int x3 = gid & 3;

        float bxv[4][2], byv[4][2];
        #pragma unroll
        for (int nt = 0; nt < 4; nt++) {
            int o0 = nbase + nt * 8 + 2 * q;
            bxv[nt][0] = __ldg(bx + o0); bxv[nt][1] = __ldg(bx + o0 + 1);
            byv[nt][0] = __ldg(by + o0); byv[nt][1] = __ldg(by + o0 + 1);
        }

        uint32_t abm[4];
        #pragma unroll
        for (int m = 0; m < 4; m++) {
            int px = mbase + gid + 8 * m;
            abm[m] = (uint32_t)px * 256u + (uint32_t)((q ^ (gid >> 1)) << 4);
        }
        // B base: row = (k16*4 + q), col o = nbase + gid (cell 16B)
        const char* pB = smW + q * WPITCH + (nbase + gid) * 16;

        int s = 0;
        for (int t = blockIdx.x; t < NTILES; t += grid) {
            float acc[2][2][4][4];
            #pragma unroll
            for (int g = 0; g < 2; g++)
                #pragma unroll
                for (int mt = 0; mt < 2; mt++)
                    #pragma unroll
                    for (int nt = 0; nt < 4; nt++)
                        #pragma unroll
                        for (int i = 0; i < 4; i++) acc[g][mt][nt][i] = 0.f;

            #pragma unroll
            for (int ch = 0; ch < 2; ch++, s++) {
                WAIT_PARITY(sbase + S_MB + (s & 3) * 8, (s >> 2) & 1);
                const char* hb = smem + S_HALF + (s & 3) * 16384;

                #pragma unroll
                for (int k16l = 0; k16l < 4; k16l++) {
                    const uint32_t koff = (uint32_t)((k16l ^ x3) << 6);
                    uint4 A0 = *(const uint4*)(hb + abm[0] + koff);
                    uint4 A1 = *(const uint4*)(hb + abm[1] + koff);
                    uint4 A2 = *(const uint4*)(hb + abm[2] + koff);
                    uint4 A3 = *(const uint4*)(hb + abm[3] + koff);
                    const char* _pb = pB + (ch * 4 + k16l) * (4 * WPITCH);
                    #pragma unroll
                    for (int nt = 0; nt < 4; nt++) {
                        uint4 B = *(const uint4*)(_pb + nt * 128);
                        mma_f16(acc[0][0][nt], A0.x, A1.x, A0.y, A1.y, B.x, B.y);
                        mma_f16(acc[0][1][nt], A2.x, A3.x, A2.y, A3.y, B.x, B.y);
                        mma_f16(acc[1][0][nt], A0.z, A1.z, A0.w, A1.w, B.z, B.w);
                        mma_f16(acc[1][1][nt], A2.z, A3.z, A2.w, A3.w, B.z, B.w);
                    }
                }
                MB_ARRIVE(sbase + S_MB + 32 + (s & 3) * 8);
            }

            // ---- epilogue ----
            const int b = t >> 10, pp = (t & 1023) << 6;
            const size_t tb = ((size_t)b << 23) + (size_t)pp;
            #pragma unroll
            for (int nt = 0; nt < 4; nt++) {
                const int o0 = nbase + nt * 8 + 2 * q;
                #pragma unroll
                for (int io = 0; io < 2; io++) {
                    float2* rowp = out + tb + ((size_t)(o0 + io) << 16);
                    #pragma unroll
                    for (int mt = 0; mt < 2; mt++) {
                        #pragma unroll
                        for (int ih = 0; ih < 2; ih++) {
                            const int pix = mbase + mt * 16 + gid + ih * 8;
                            float a = acc[0][mt][nt][ih * 2 + io] + bxv[nt][io];
                            float g = acc[1][mt][nt][ih * 2 + io] + byv[nt][io];
                            rowp[pix] = make_float2(fmaxf(a, 0.f), g);
                        }
                    }
                }
            }
        }
    }
}

extern "C" void kernel_launch(void* const* d_in, const int* in_sizes, int n_in,
                              void* d_out, int out_size) {
    const float* x  = (const float*)d_in[0];
    const float* wx = (const float*)d_in[1];
    const float* bx = (const float*)d_in[2];
    const float* wy = (const float*)d_in[3];
    const float* by = (const float*)d_in[4];
    float2* out = (float2*)d_out;

    int nsm = 148;
    cudaDeviceGetAttribute(&nsm, cudaDevAttrMultiProcessorCount, 0);

    cudaFuncSetAttribute(avnn_w9, cudaFuncAttributeMaxDynamicSharedMemorySize,
                         SMEM_TOTAL);
    avnn_w9<<<nsm, 384, SMEM_TOTAL>>>(x, wx, bx, wy, by, out);
}